// round 7
// baseline (speedup 1.0000x reference)
#include <cuda_runtime.h>
#include <cuda_fp16.h>
#include <cstdint>

// UnionLayer via Taylor expansion -> fp16 tensor-core GEMM (mma.sync, generic PTX).
//   -log(1-t) = sum_{n=1..7} t^n / n,  t = u*w in [0, 0.5)
//   S[b,nh]   = sum_d sum_n u^n * (w^n / n)  == GEMM, K = 7*512
//   con: u = 1-x, y = 1/(1+S);  dis: u = x, y = 1 - 1/(1+S)
// R7: 512-thread CTA, in-CTA split-K x4:
//   warp w: m-slice (w&3)*32, d-quarter (w>>2)*128 (4 chunks of 32 d)
//   -> 16 warps/SM (4/SMSP) for latency hiding; partials reduced via smem.
// Operands generated in registers in mma fragment layout (no smem in mainloop).
// Grid (8, 8, 2) = 128 CTAs.

#define DDIM    512
#define NOUT    512
#define NCOLS   256
#define NTERMS  7
#define DCHUNK  32
#define MTILE   128
#define NTILE   32
#define THREADS 512
#define RED_BYTES (16 * 32 * 32 * 4)   // 65536

__device__ __forceinline__ void mma16816(float* c, uint32_t a0, uint32_t a1,
                                         uint32_t a2, uint32_t a3,
                                         uint32_t b0, uint32_t b1) {
    asm volatile(
        "mma.sync.aligned.m16n8k16.row.col.f32.f16.f16.f32 "
        "{%0,%1,%2,%3}, {%4,%5,%6,%7}, {%8,%9}, {%0,%1,%2,%3};"
        : "+f"(c[0]), "+f"(c[1]), "+f"(c[2]), "+f"(c[3])
        : "r"(a0), "r"(a1), "r"(a2), "r"(a3), "r"(b0), "r"(b1));
}

__device__ __forceinline__ uint32_t h2u(__half2 h) {
    return *reinterpret_cast<uint32_t*>(&h);
}

__global__ __launch_bounds__(THREADS) void union_mma_kernel(
    const float* __restrict__ x,
    const float* __restrict__ Wcon,
    const float* __restrict__ Wdis,
    float* __restrict__ out)
{
    extern __shared__ float red[];     // [warp][32m][32n] partial S tiles

    const int tid  = threadIdx.x;
    const int wid  = tid >> 5;
    const int lane = tid & 31;
    const int g    = lane >> 2;        // 0..7
    const int t4   = lane & 3;         // 0..3
    const int ms   = (wid & 3) * 32;   // m-slice within CTA tile
    const int gk0  = (wid >> 2) * 128; // d-quarter base
    const int bn0  = blockIdx.x * NTILE;
    const int bm0  = blockIdx.y * MTILE;
    const int z    = blockIdx.z;       // 0 = con, 1 = dis
    const float* __restrict__ W = z ? Wdis : Wcon;

    const float* __restrict__ pA = &x[(bm0 + ms + g) * DDIM + gk0 + 2 * t4];
    const float* __restrict__ pB = &W[(bn0 + g) * DDIM + gk0 + 2 * t4];

    float acc[2][4][4];
#pragma unroll
    for (int mt = 0; mt < 2; mt++)
#pragma unroll
        for (int nt = 0; nt < 4; nt++)
#pragma unroll
            for (int c = 0; c < 4; c++) acc[mt][nt][c] = 0.0f;

    __half2 baseA[4][4], baseB[4][4], curA[4][4], curB[4][4];
    const float kf[NTERMS] = {0.f, 0.5f, 2.f/3.f, 0.75f, 0.8f, 5.f/6.f, 6.f/7.f};

#pragma unroll
    for (int ck = 0; ck < 4; ck++) {
        // ---- load raw chunk + build half2 bases (LDG.64, L2-resident) ----
#pragma unroll
        for (int r = 0; r < 4; r++)
#pragma unroll
            for (int p = 0; p < 4; p++) {
                float2 a = *reinterpret_cast<const float2*>(pA + r * 8 * DDIM + ck * DCHUNK + p * 8);
                float2 b = *reinterpret_cast<const float2*>(pB + r * 8 * DDIM + ck * DCHUNK + p * 8);
                float ux = a.x, uy = a.y;
                if (z == 0) { ux = 1.0f - ux; uy = 1.0f - uy; }
                baseA[r][p] = __floats2half2_rn(ux, uy);
                baseB[r][p] = __floats2half2_rn(b.x, b.y);
                curA[r][p]  = baseA[r][p];
                curB[r][p]  = baseB[r][p];
            }

        // ---- 7 Taylor terms ----
#pragma unroll
        for (int n = 0; n < NTERMS; n++) {
            if (n) {
                const __half2 kfh = __float2half2_rn(kf[n]);
#pragma unroll
                for (int r = 0; r < 4; r++)
#pragma unroll
                    for (int p = 0; p < 4; p++) {
                        curA[r][p] = __hmul2(curA[r][p], baseA[r][p]);
                        curB[r][p] = __hmul2(__hmul2(curB[r][p], baseB[r][p]), kfh);
                    }
            }
#pragma unroll
            for (int db = 0; db < 2; db++) {
                const int p0 = db * 2, p1 = db * 2 + 1;
#pragma unroll
                for (int mt = 0; mt < 2; mt++) {
                    uint32_t a0 = h2u(curA[mt * 2 + 0][p0]);
                    uint32_t a1 = h2u(curA[mt * 2 + 1][p0]);
                    uint32_t a2 = h2u(curA[mt * 2 + 0][p1]);
                    uint32_t a3 = h2u(curA[mt * 2 + 1][p1]);
#pragma unroll
                    for (int nt = 0; nt < 4; nt++) {
                        mma16816(acc[mt][nt], a0, a1, a2, a3,
                                 h2u(curB[nt][p0]), h2u(curB[nt][p1]));
                    }
                }
            }
        }
    }

    // ---- store partial 32x32 tile to smem ----
    float* tile = &red[wid * 1024];
#pragma unroll
    for (int mt = 0; mt < 2; mt++)
#pragma unroll
        for (int half = 0; half < 2; half++) {
            int r = mt * 16 + half * 8 + g;
#pragma unroll
            for (int nt = 0; nt < 4; nt++) {
                *reinterpret_cast<float2*>(&tile[r * 32 + nt * 8 + 2 * t4]) =
                    make_float2(acc[mt][nt][half * 2 + 0], acc[mt][nt][half * 2 + 1]);
            }
        }
    __syncthreads();

    // ---- reduce 4 d-quarters + epilogue ----
    // thread handles m = tid>>2 (0..127), n = (tid&3)*8 .. +7
    {
        const int m  = tid >> 2;
        const int n0 = (tid & 3) * 8;
        const int msb = m >> 5;          // which m-slice
        const int r   = m & 31;
        float v[8];
#pragma unroll
        for (int j = 0; j < 8; j++) {
            float S = 0.0f;
#pragma unroll
            for (int q = 0; q < 4; q++)
                S += red[(q * 4 + msb) * 1024 + r * 32 + n0 + j];
            float y = 1.0f / (1.0f + S);
            v[j] = z ? (1.0f - y) : y;
        }
        float* dst = &out[(bm0 + m) * NOUT + z * NCOLS + bn0 + n0];
        *reinterpret_cast<float4*>(dst)     = make_float4(v[0], v[1], v[2], v[3]);
        *reinterpret_cast<float4*>(dst + 4) = make_float4(v[4], v[5], v[6], v[7]);
    }
}

extern "C" void kernel_launch(void* const* d_in, const int* in_sizes, int n_in,
                              void* d_out, int out_size)
{
    const float* x    = (const float*)d_in[0];
    const float* Wcon = (const float*)d_in[1];
    const float* Wdis = (const float*)d_in[2];
    float* out = (float*)d_out;

    cudaFuncSetAttribute(union_mma_kernel,
                         cudaFuncAttributeMaxDynamicSharedMemorySize, RED_BYTES);

    dim3 grid(NCOLS / NTILE, 1024 / MTILE, 2);   // (8, 8, 2) = 128 CTAs
    union_mma_kernel<<<grid, THREADS, RED_BYTES>>>(x, Wcon, Wdis, out);
}

// round 8
// speedup vs baseline: 1.2892x; 1.2892x over previous
#include <cuda_runtime.h>
#include <cuda_fp16.h>
#include <cstdint>

// UnionLayer via Taylor expansion -> fp16 tensor-core GEMM (mma.sync, generic PTX).
//   -log(1-t) = sum_{n=1..7} t^n / n,  t = u*w in [0, 0.5)
//   S[b,nh]   = sum_d sum_n u^n * (w^n / n)  == GEMM, K = 7*512
//   con: u = 1-x, y = 1/(1+S);  dis: u = x, y = 1 - 1/(1+S)
// R8 = R6 inner loop (register fragments + software prefetch) x split-K2:
//   256-thread CTA, 8 warps: m-slice (w&3)*32, d-half (w>>2)*256
//   -> 2 warps/SMSP (vs R6's 1) with NO register cap (256 thr -> 255 regs ok).
//   16KB smem reduction merges the two d-halves at the end.
// Grid (8, 8, 2) = 128 CTAs, 1 per SM.

#define DDIM    512
#define NOUT    512
#define NCOLS   256
#define NTERMS  7
#define DCHUNK  32
#define NCHW    8          // chunks per warp (256 d / 32)
#define MTILE   128
#define NTILE   32
#define THREADS 256

__device__ __forceinline__ void mma16816(float* c, uint32_t a0, uint32_t a1,
                                         uint32_t a2, uint32_t a3,
                                         uint32_t b0, uint32_t b1) {
    asm volatile(
        "mma.sync.aligned.m16n8k16.row.col.f32.f16.f16.f32 "
        "{%0,%1,%2,%3}, {%4,%5,%6,%7}, {%8,%9}, {%0,%1,%2,%3};"
        : "+f"(c[0]), "+f"(c[1]), "+f"(c[2]), "+f"(c[3])
        : "r"(a0), "r"(a1), "r"(a2), "r"(a3), "r"(b0), "r"(b1));
}

__device__ __forceinline__ uint32_t h2u(__half2 h) {
    return *reinterpret_cast<uint32_t*>(&h);
}

__global__ __launch_bounds__(THREADS) void union_mma_kernel(
    const float* __restrict__ x,
    const float* __restrict__ Wcon,
    const float* __restrict__ Wdis,
    float* __restrict__ out)
{
    __shared__ float red[4][32][32];   // d-half-1 partial tiles (16 KB)

    const int tid  = threadIdx.x;
    const int wid  = tid >> 5;
    const int lane = tid & 31;
    const int g    = lane >> 2;        // 0..7
    const int t4   = lane & 3;         // 0..3
    const int msl  = wid & 3;          // m-slice index
    const int dh   = wid >> 2;         // d-half 0/1
    const int gk0  = dh * 256;
    const int bn0  = blockIdx.x * NTILE;
    const int bm0  = blockIdx.y * MTILE;
    const int z    = blockIdx.z;       // 0 = con, 1 = dis
    const float* __restrict__ W = z ? Wdis : Wcon;

    const float* __restrict__ pA = &x[(bm0 + msl * 32 + g) * DDIM + gk0 + 2 * t4];
    const float* __restrict__ pB = &W[(bn0 + g) * DDIM + gk0 + 2 * t4];

    float acc[2][4][4];
#pragma unroll
    for (int mt = 0; mt < 2; mt++)
#pragma unroll
        for (int nt = 0; nt < 4; nt++)
#pragma unroll
            for (int c = 0; c < 4; c++) acc[mt][nt][c] = 0.0f;

    // staged raw loads (software prefetch): [row][dpair]
    float2 fA[4][4], fB[4][4];
#pragma unroll
    for (int r = 0; r < 4; r++)
#pragma unroll
        for (int p = 0; p < 4; p++) {
            fA[r][p] = *reinterpret_cast<const float2*>(pA + r * 8 * DDIM + p * 8);
            fB[r][p] = *reinterpret_cast<const float2*>(pB + r * 8 * DDIM + p * 8);
        }

    __half2 baseA[4][4], baseB[4][4], curA[4][4], curB[4][4];
    const float kf[NTERMS] = {0.f, 0.5f, 2.f/3.f, 0.75f, 0.8f, 5.f/6.f, 6.f/7.f};

#pragma unroll 1
    for (int ck = 0; ck < NCHW; ck++) {
        // ---- convert staged floats -> half2 bases ----
#pragma unroll
        for (int r = 0; r < 4; r++)
#pragma unroll
            for (int p = 0; p < 4; p++) {
                float ux = fA[r][p].x, uy = fA[r][p].y;
                if (z == 0) { ux = 1.0f - ux; uy = 1.0f - uy; }
                baseA[r][p] = __floats2half2_rn(ux, uy);
                baseB[r][p] = __floats2half2_rn(fB[r][p].x, fB[r][p].y);
                curA[r][p]  = baseA[r][p];
                curB[r][p]  = baseB[r][p];
            }

        // ---- prefetch next chunk raw (hidden under term loop) ----
        if (ck + 1 < NCHW) {
            const float* qA = pA + (ck + 1) * DCHUNK;
            const float* qB = pB + (ck + 1) * DCHUNK;
#pragma unroll
            for (int r = 0; r < 4; r++)
#pragma unroll
                for (int p = 0; p < 4; p++) {
                    fA[r][p] = *reinterpret_cast<const float2*>(qA + r * 8 * DDIM + p * 8);
                    fB[r][p] = *reinterpret_cast<const float2*>(qB + r * 8 * DDIM + p * 8);
                }
        }

        // ---- 7 Taylor terms ----
#pragma unroll
        for (int n = 0; n < NTERMS; n++) {
            if (n) {
                const __half2 kfh = __float2half2_rn(kf[n]);
#pragma unroll
                for (int r = 0; r < 4; r++)
#pragma unroll
                    for (int p = 0; p < 4; p++) {
                        curA[r][p] = __hmul2(curA[r][p], baseA[r][p]);
                        curB[r][p] = __hmul2(__hmul2(curB[r][p], baseB[r][p]), kfh);
                    }
            }
#pragma unroll
            for (int db = 0; db < 2; db++) {
                const int p0 = db * 2, p1 = db * 2 + 1;
#pragma unroll
                for (int mt = 0; mt < 2; mt++) {
                    uint32_t a0 = h2u(curA[mt * 2 + 0][p0]);
                    uint32_t a1 = h2u(curA[mt * 2 + 1][p0]);
                    uint32_t a2 = h2u(curA[mt * 2 + 0][p1]);
                    uint32_t a3 = h2u(curA[mt * 2 + 1][p1]);
#pragma unroll
                    for (int nt = 0; nt < 4; nt++) {
                        mma16816(acc[mt][nt], a0, a1, a2, a3,
                                 h2u(curB[nt][p0]), h2u(curB[nt][p1]));
                    }
                }
            }
        }
    }

    // ---- merge d-halves: half 1 stores, half 0 adds + epilogue ----
    if (dh == 1) {
#pragma unroll
        for (int mt = 0; mt < 2; mt++)
#pragma unroll
            for (int half = 0; half < 2; half++) {
                int r = mt * 16 + half * 8 + g;
#pragma unroll
                for (int nt = 0; nt < 4; nt++) {
                    *reinterpret_cast<float2*>(&red[msl][r][nt * 8 + 2 * t4]) =
                        make_float2(acc[mt][nt][half * 2 + 0],
                                    acc[mt][nt][half * 2 + 1]);
                }
            }
    }
    __syncthreads();

    if (dh == 0) {
#pragma unroll
        for (int mt = 0; mt < 2; mt++) {
#pragma unroll
            for (int half = 0; half < 2; half++) {
                int r = mt * 16 + half * 8 + g;
                int m = bm0 + msl * 32 + r;
#pragma unroll
                for (int nt = 0; nt < 4; nt++) {
                    float2 o = *reinterpret_cast<const float2*>(&red[msl][r][nt * 8 + 2 * t4]);
                    float S0 = acc[mt][nt][half * 2 + 0] + o.x;
                    float S1 = acc[mt][nt][half * 2 + 1] + o.y;
                    float y0 = 1.0f / (1.0f + S0);
                    float y1 = 1.0f / (1.0f + S1);
                    if (z) { y0 = 1.0f - y0; y1 = 1.0f - y1; }
                    int col = bn0 + nt * 8 + 2 * t4;
                    *reinterpret_cast<float2*>(&out[m * NOUT + z * NCOLS + col]) =
                        make_float2(y0, y1);
                }
            }
        }
    }
}

extern "C" void kernel_launch(void* const* d_in, const int* in_sizes, int n_in,
                              void* d_out, int out_size)
{
    const float* x    = (const float*)d_in[0];
    const float* Wcon = (const float*)d_in[1];
    const float* Wdis = (const float*)d_in[2];
    float* out = (float*)d_out;

    dim3 grid(NCOLS / NTILE, 1024 / MTILE, 2);   // (8, 8, 2) = 128 CTAs
    union_mma_kernel<<<grid, THREADS>>>(x, Wcon, Wdis, out);
}